// round 15
// baseline (speedup 1.0000x reference)
#include <cuda_runtime.h>
#include <cstdint>

// Binarize: x[4096, 8192] fp32, depth[3] -> out[4096, 3, 1024] float32,
// each output element = numeric value of the big-endian packed byte.
//
// R15: R14's loop-free one-shot body (best kernel time, 24.06us, DRAM 74.6%)
// repackaged as block=1024 / grid=4096 to cut CTA count 4x: R14's 16384
// one-iteration CTAs inflated the per-replay launch/drain overhead (wall gap
// 5.0us vs 2.7us for the persistent kernel). Memory policy unchanged from
// the champion: 8 consecutive floats/thread (32B lane stride, L1-optimal),
// .cs loads, .cg stores (output stays L2-resident across graph replays),
// float-accumulation pack on the fma pipe (exact for sums of distinct
// powers of two <= 255).

#define COLS 8192
#define BPR  (COLS / 8)     // 1024 packed bytes (output floats) per row per plane

__global__ __launch_bounds__(1024) void binarize_kernel(
    const float* __restrict__ x,
    const float* __restrict__ depth,
    float* __restrict__ out)
{
    const int c = blockIdx.x * blockDim.x + threadIdx.x;  // chunk index

    const float d0 = __ldg(depth + 0);
    const float d1 = __ldg(depth + 1);
    const float d2 = __ldg(depth + 2);

    const float4* __restrict__ x4 = reinterpret_cast<const float4*>(x);
    const float4 a = __ldcs(x4 + 2 * (size_t)c);
    const float4 b = __ldcs(x4 + 2 * (size_t)c + 1);

    // Pack via float accumulation (fma pipe). Big-endian: weight 2^(7-e).
    const float f[8] = { a.x, a.y, a.z, a.w, b.x, b.y, b.z, b.w };
    float a0 = 0.0f, a1 = 0.0f, a2 = 0.0f;
#pragma unroll
    for (int e = 0; e < 8; e++) {
        const float w = (float)(1u << (7 - e));   // compile-time constant
        if (f[e] > d0) a0 += w;
        if (f[e] > d1) a1 += w;
        if (f[e] > d2) a2 += w;
    }

    const int row = c >> 10;           // c / BPR
    const int t   = c & (BPR - 1);
    float* o = out + (size_t)row * (3 * BPR) + t;
    __stcg(o,           a0);
    __stcg(o + BPR,     a1);
    __stcg(o + 2 * BPR, a2);
}

extern "C" void kernel_launch(void* const* d_in, const int* in_sizes, int n_in,
                              void* d_out, int out_size) {
    const float* x     = (const float*)d_in[0];
    const float* depth = (const float*)d_in[1];
    float*       out   = (float*)d_out;

    const int n       = in_sizes[0];   // 4096 * 8192
    const int nchunks = n / 8;         // 4,194,304 (multiple of 1024)

    const int block = 1024;
    const int grid  = nchunks / block; // 4096 one-shot CTAs

    binarize_kernel<<<grid, block>>>(x, depth, out);
}

// round 16
// speedup vs baseline: 1.0707x; 1.0707x over previous
#include <cuda_runtime.h>
#include <cstdint>

// Binarize: x[4096, 8192] fp32, depth[3] -> out[4096, 3, 1024] float32,
// each output element = numeric value of the big-endian packed byte.
//
// FINAL champion (R7 = R13, 27.36-27.39us wall / ~24.3us kernel, DRAM ~73%):
//  - thread owns 8 consecutive floats (2x LDG.128, 32B lane stride ->
//    L1-wavefront-optimal; 64B/128B strides measured 1.1-1.4x slower)
//  - pack via float accumulation on the fma pipe: if f>d acc += 2^(7-e).
//    Exact (sums of distinct powers of two <= 255); removes all I2F and
//    integer mask ops from the congested alu pipe (-1.5us vs int pack).
//  - loads .cs (streaming, evict-first); stores .cg so the 50MB output stays
//    L2-resident across graph replays (-1.1us kernel / -2.7us wall).
//  - register double-buffer pipeline; persistent 1184x256 grid (8 CTA/SM):
//    one-shot launches (16384x256, 4096x1024) had equal-or-better kernel
//    time but 2-3us worse wall (replay launch/drain overhead).
//  - refuted alternatives: MLP=4 unrolls (neutral), read-residency L2
//    pinning (no effect twice), wider per-thread chunks (L1 wavefronts
//    scale with lane stride).

#define COLS 8192
#define BPR  (COLS / 8)     // 1024 packed bytes (output floats) per row per plane

__global__ __launch_bounds__(256) void binarize_kernel(
    const float* __restrict__ x,
    const float* __restrict__ depth,
    float* __restrict__ out,
    int nchunks)            // total 8-element chunks = n/8
{
    const float d0 = __ldg(depth + 0);
    const float d1 = __ldg(depth + 1);
    const float d2 = __ldg(depth + 2);

    const float4* __restrict__ x4 = reinterpret_cast<const float4*>(x);

    const int stride = gridDim.x * blockDim.x;
    int c = blockIdx.x * blockDim.x + threadIdx.x;
    if (c >= nchunks) return;

    // Prologue: prefetch first chunk.
    float4 a = __ldcs(x4 + 2 * (size_t)c);
    float4 b = __ldcs(x4 + 2 * (size_t)c + 1);

#pragma unroll 1
    while (true) {
        const int cn = c + stride;
        const bool more = (cn < nchunks);

        // Issue next chunk's loads immediately (overlap with pack below).
        float4 an, bn;
        if (more) {
            an = __ldcs(x4 + 2 * (size_t)cn);
            bn = __ldcs(x4 + 2 * (size_t)cn + 1);
        }

        // Pack current chunk via float accumulation (fma pipe).
        // Big-endian: element e has weight 2^(7-e).
        const float f[8] = { a.x, a.y, a.z, a.w, b.x, b.y, b.z, b.w };
        float a0 = 0.0f, a1 = 0.0f, a2 = 0.0f;
#pragma unroll
        for (int e = 0; e < 8; e++) {
            const float w = (float)(1u << (7 - e));   // compile-time constant
            if (f[e] > d0) a0 += w;
            if (f[e] > d1) a1 += w;
            if (f[e] > d2) a2 += w;
        }

        const int row = c >> 10;           // c / BPR
        const int t   = c & (BPR - 1);
        float* o = out + (size_t)row * (3 * BPR) + t;
        __stcg(o,           a0);
        __stcg(o + BPR,     a1);
        __stcg(o + 2 * BPR, a2);

        if (!more) break;
        a = an; b = bn; c = cn;
    }
}

extern "C" void kernel_launch(void* const* d_in, const int* in_sizes, int n_in,
                              void* d_out, int out_size) {
    const float* x     = (const float*)d_in[0];
    const float* depth = (const float*)d_in[1];
    float*       out   = (float*)d_out;

    const int n       = in_sizes[0];   // 4096 * 8192
    const int nchunks = n / 8;

    const int block = 256;
    int grid = 148 * 8;                // persistent: 8 blocks/SM
    const int max_grid = (nchunks + block - 1) / block;
    if (grid > max_grid) grid = max_grid;

    binarize_kernel<<<grid, block>>>(x, depth, out, nchunks);
}

// round 17
// speedup vs baseline: 1.0789x; 1.0077x over previous
#include <cuda_runtime.h>
#include <cstdint>

// Binarize: x[4096, 8192] fp32, depth[3] -> out[4096, 3, 1024] float32,
// each output element = numeric value of the big-endian packed byte.
//
// FINAL champion (R7/R13/R16; wall 27.36-29.41us across 3 runs, +-1-2us
// bench noise; kernel 24.3-25.7us, DRAM 70-74% = binding pipe):
//  - thread owns 8 consecutive floats (2x LDG.128, 32B lane stride ->
//    L1-wavefront-optimal; 64B/128B strides measured 1.1-1.4x slower)
//  - pack via float accumulation on the fma pipe: if f>d acc += 2^(7-e).
//    Exact (sums of distinct powers of two <= 255); removes all I2F and
//    integer mask ops from the congested alu pipe (-1.5us vs int pack).
//  - loads .cs (streaming, evict-first); stores .cg so the 50MB output stays
//    L2-resident across graph replays (-1.1us kernel / -2.7us wall).
//  - register double-buffer pipeline; persistent 1184x256 grid (8 CTA/SM):
//    one-shot launches had equal kernel time but 2-3us worse wall.
//  - refuted: MLP=4 unrolls (neutral), read-residency L2 pinning (no effect,
//    twice), wider per-thread chunks (L1 wavefronts scale with lane stride).

#define COLS 8192
#define BPR  (COLS / 8)     // 1024 packed bytes (output floats) per row per plane

__global__ __launch_bounds__(256) void binarize_kernel(
    const float* __restrict__ x,
    const float* __restrict__ depth,
    float* __restrict__ out,
    int nchunks)            // total 8-element chunks = n/8
{
    const float d0 = __ldg(depth + 0);
    const float d1 = __ldg(depth + 1);
    const float d2 = __ldg(depth + 2);

    const float4* __restrict__ x4 = reinterpret_cast<const float4*>(x);

    const int stride = gridDim.x * blockDim.x;
    int c = blockIdx.x * blockDim.x + threadIdx.x;
    if (c >= nchunks) return;

    // Prologue: prefetch first chunk.
    float4 a = __ldcs(x4 + 2 * (size_t)c);
    float4 b = __ldcs(x4 + 2 * (size_t)c + 1);

#pragma unroll 1
    while (true) {
        const int cn = c + stride;
        const bool more = (cn < nchunks);

        // Issue next chunk's loads immediately (overlap with pack below).
        float4 an, bn;
        if (more) {
            an = __ldcs(x4 + 2 * (size_t)cn);
            bn = __ldcs(x4 + 2 * (size_t)cn + 1);
        }

        // Pack current chunk via float accumulation (fma pipe).
        // Big-endian: element e has weight 2^(7-e).
        const float f[8] = { a.x, a.y, a.z, a.w, b.x, b.y, b.z, b.w };
        float a0 = 0.0f, a1 = 0.0f, a2 = 0.0f;
#pragma unroll
        for (int e = 0; e < 8; e++) {
            const float w = (float)(1u << (7 - e));   // compile-time constant
            if (f[e] > d0) a0 += w;
            if (f[e] > d1) a1 += w;
            if (f[e] > d2) a2 += w;
        }

        const int row = c >> 10;           // c / BPR
        const int t   = c & (BPR - 1);
        float* o = out + (size_t)row * (3 * BPR) + t;
        __stcg(o,           a0);
        __stcg(o + BPR,     a1);
        __stcg(o + 2 * BPR, a2);

        if (!more) break;
        a = an; b = bn; c = cn;
    }
}

extern "C" void kernel_launch(void* const* d_in, const int* in_sizes, int n_in,
                              void* d_out, int out_size) {
    const float* x     = (const float*)d_in[0];
    const float* depth = (const float*)d_in[1];
    float*       out   = (float*)d_out;

    const int n       = in_sizes[0];   // 4096 * 8192
    const int nchunks = n / 8;

    const int block = 256;
    int grid = 148 * 8;                // persistent: 8 blocks/SM
    const int max_grid = (nchunks + block - 1) / block;
    if (grid > max_grid) grid = max_grid;

    binarize_kernel<<<grid, block>>>(x, depth, out, nchunks);
}